// round 3
// baseline (speedup 1.0000x reference)
#include <cuda_runtime.h>
#include <cuda_bf16.h>
#include <cstdint>

// Problem constants
constexpr int BATCH = 4;
constexpr int T     = 2048;
constexpr int NH    = 16;
constexpr int DH    = 64;
constexpr int DM    = 1024;      // NH*DH
constexpr int MROWS = BATCH * T; // 8192

// Scratch (device globals; no allocation allowed)
__device__ float g_qkv[(size_t)MROWS * 3 * DM]; // [B*T, 3*DM]
__device__ float g_ctx[(size_t)MROWS * DM];     // context [B*T, DM]
__device__ float g_m [(size_t)BATCH * NH * T];  // row max
__device__ float g_si[(size_t)BATCH * NH * T];  // row 1/sumexp

constexpr int SK = 40;  // smem tile k-stride in bf16 (32 + 8 pad)
constexpr int S2 = 20;  // same in uint32 (bf16x2) units

__device__ __forceinline__ float ninf() { return __int_as_float(0xff800000u); }

// Split two floats into packed bf16 hi/lo pairs.
__device__ __forceinline__ void split2(float x, float y, uint32_t& h, uint32_t& l) {
    __nv_bfloat162 hh, ll;
    hh.x = __float2bfloat16(x);
    hh.y = __float2bfloat16(y);
    ll.x = __float2bfloat16(x - __bfloat162float(hh.x));
    ll.y = __float2bfloat16(y - __bfloat162float(hh.y));
    h = *reinterpret_cast<uint32_t*>(&hh);
    l = *reinterpret_cast<uint32_t*>(&ll);
}
__device__ __forceinline__ void split1(float x, __nv_bfloat16& h, __nv_bfloat16& l) {
    h = __float2bfloat16(x);
    l = __float2bfloat16(x - __bfloat162float(h));
}

__device__ __forceinline__ void mma16816(float* c, const uint32_t* a, const uint32_t* b) {
    asm volatile(
        "mma.sync.aligned.m16n8k16.row.col.f32.bf16.bf16.f32 "
        "{%0,%1,%2,%3}, {%4,%5,%6,%7}, {%8,%9}, {%0,%1,%2,%3};\n"
        : "+f"(c[0]), "+f"(c[1]), "+f"(c[2]), "+f"(c[3])
        : "r"(a[0]), "r"(a[1]), "r"(a[2]), "r"(a[3]), "r"(b[0]), "r"(b[1]));
}

// A fragment (m16k16) from smem laid out [m][k], k-stride S2 uint32.
__device__ __forceinline__ void ldA(uint32_t a[4], const uint32_t* S, int m0, int k2, int lane) {
    const uint32_t* p = S + (size_t)(m0 + (lane >> 2)) * S2 + k2 + (lane & 3);
    a[0] = p[0];
    a[1] = p[8 * S2];
    a[2] = p[4];
    a[3] = p[8 * S2 + 4];
}
// B fragment (k16n8) from smem laid out [n][k], k-stride S2 uint32.
__device__ __forceinline__ void ldB(uint32_t b[2], const uint32_t* S, int n0, int k2, int lane) {
    const uint32_t* p = S + (size_t)(n0 + (lane >> 2)) * S2 + k2 + (lane & 3);
    b[0] = p[0];
    b[1] = p[4];
}

// ---------------------------------------------------------------------------
// Projection GEMM: C[M,N] = A[M,K] @ B[K,N] + bias. 256 thr, BM=BN=128, BK=32.
// 8 warps (2m x 4n), warp tile 64x32, bf16 hi/lo split (3 mma per tile).
// ---------------------------------------------------------------------------
__global__ __launch_bounds__(256) void gemm_bias_tc(
    const float* __restrict__ A, const float* __restrict__ B,
    const float* __restrict__ bias, float* __restrict__ C,
    int M, int N, int K)
{
    __shared__ __nv_bfloat16 AsH[128 * SK], AsL[128 * SK];
    __shared__ __nv_bfloat16 BsH[128 * SK], BsL[128 * SK];

    const int tid = threadIdx.x, lane = tid & 31, w = tid >> 5;
    const int row0 = blockIdx.y * 128, col0 = blockIdx.x * 128;
    const int wm = (w & 1) * 64, wn = (w >> 1) * 32;

    float acc[4][4][4];
#pragma unroll
    for (int i = 0; i < 4; i++)
#pragma unroll
        for (int j = 0; j < 4; j++)
#pragma unroll
            for (int e = 0; e < 4; e++) acc[i][j][e] = 0.f;

    for (int k0 = 0; k0 < K; k0 += 32) {
        // A tile 128x32 -> [m][k]
#pragma unroll
        for (int ps = 0; ps < 4; ps++) {
            int r = (tid >> 3) + ps * 32;
            int c4 = tid & 7;
            float4 v = *(const float4*)&A[(size_t)(row0 + r) * K + k0 + c4 * 4];
            uint32_t h0, l0, h1, l1;
            split2(v.x, v.y, h0, l0);
            split2(v.z, v.w, h1, l1);
            ((uint32_t*)AsH)[r * S2 + c4 * 2]     = h0;
            ((uint32_t*)AsH)[r * S2 + c4 * 2 + 1] = h1;
            ((uint32_t*)AsL)[r * S2 + c4 * 2]     = l0;
            ((uint32_t*)AsL)[r * S2 + c4 * 2 + 1] = l1;
        }
        // B tile 32x128 -> transposed [n][k]
#pragma unroll
        for (int ps = 0; ps < 4; ps++) {
            int kr = (tid >> 5) + ps * 8;
            int c4 = tid & 31;
            float4 v = *(const float4*)&B[(size_t)(k0 + kr) * N + col0 + c4 * 4];
            int n = c4 * 4;
            __nv_bfloat16 h, l;
            split1(v.x, h, l); BsH[(n + 0) * SK + kr] = h; BsL[(n + 0) * SK + kr] = l;
            split1(v.y, h, l); BsH[(n + 1) * SK + kr] = h; BsL[(n + 1) * SK + kr] = l;
            split1(v.z, h, l); BsH[(n + 2) * SK + kr] = h; BsL[(n + 2) * SK + kr] = l;
            split1(v.w, h, l); BsH[(n + 3) * SK + kr] = h; BsL[(n + 3) * SK + kr] = l;
        }
        __syncthreads();

#pragma unroll
        for (int ks = 0; ks < 2; ks++) {
            uint32_t aH[4][4], aL[4][4];
#pragma unroll
            for (int i = 0; i < 4; i++) {
                ldA(aH[i], (const uint32_t*)AsH, wm + i * 16, ks * 8, lane);
                ldA(aL[i], (const uint32_t*)AsL, wm + i * 16, ks * 8, lane);
            }
#pragma unroll
            for (int j = 0; j < 4; j++) {
                uint32_t bH[2], bL[2];
                ldB(bH, (const uint32_t*)BsH, wn + j * 8, ks * 8, lane);
                ldB(bL, (const uint32_t*)BsL, wn + j * 8, ks * 8, lane);
#pragma unroll
                for (int i = 0; i < 4; i++) {
                    mma16816(acc[i][j], aH[i], bH);
                    mma16816(acc[i][j], aH[i], bL);
                    mma16816(acc[i][j], aL[i], bH);
                }
            }
        }
        __syncthreads();
    }

    const int r = lane >> 2, c2 = (lane & 3) * 2;
#pragma unroll
    for (int i = 0; i < 4; i++) {
#pragma unroll
        for (int j = 0; j < 4; j++) {
            int m = row0 + wm + i * 16 + r;
            int n = col0 + wn + j * 8 + c2;
            float b0 = bias[n], b1 = bias[n + 1];
            *(float2*)&C[(size_t)m * N + n] =
                make_float2(acc[i][j][0] + b0, acc[i][j][1] + b1);
            *(float2*)&C[(size_t)(m + 8) * N + n] =
                make_float2(acc[i][j][2] + b0, acc[i][j][3] + b1);
        }
    }
}

// ---------------------------------------------------------------------------
// Scores: S = Q@K^T * 0.125 (masked, zeros above diag) into weights buffer.
// Tile 128q x 128k x (d=64 in two 32-chunks). grid (T/128, T/128, B*NH).
// ---------------------------------------------------------------------------
__global__ __launch_bounds__(256) void score_tc(float* __restrict__ weights)
{
    const int k0t = blockIdx.x * 128;
    const int q0  = blockIdx.y * 128;
    const int bh  = blockIdx.z;
    const int b = bh >> 4, h = bh & 15;
    const int tid = threadIdx.x;
    float* wbase = weights + ((size_t)bh * T + q0) * T + k0t;

    if (k0t >= q0 + 128) {           // strictly-future tile: zero fill
        float4 z = make_float4(0.f, 0.f, 0.f, 0.f);
#pragma unroll
        for (int jj = 0; jj < 16; jj++) {
            int g = tid + 256 * jj;
            *(float4*)&wbase[(size_t)(g >> 5) * T + (g & 31) * 4] = z;
        }
        return;
    }

    __shared__ __nv_bfloat16 QsH[128 * SK], QsL[128 * SK];
    __shared__ __nv_bfloat16 KsH[128 * SK], KsL[128 * SK];
    const int lane = tid & 31, w = tid >> 5;
    const int wm = (w & 1) * 64, wn = (w >> 1) * 32;

    float acc[4][4][4];
#pragma unroll
    for (int i = 0; i < 4; i++)
#pragma unroll
        for (int j = 0; j < 4; j++)
#pragma unroll
            for (int e = 0; e < 4; e++) acc[i][j][e] = 0.f;

    const float* qkv = g_qkv;
#pragma unroll
    for (int dc = 0; dc < 64; dc += 32) {
#pragma unroll
        for (int ps = 0; ps < 4; ps++) {
            int r = (tid >> 3) + ps * 32;
            int c4 = tid & 7;
            uint32_t h0, l0, h1, l1;
            // Q rows [m][k]
            float4 v = *(const float4*)&qkv[((size_t)(b * T + q0 + r)) * (3 * DM) + h * DH + dc + c4 * 4];
            split2(v.x, v.y, h0, l0);
            split2(v.z, v.w, h1, l1);
            ((uint32_t*)QsH)[r * S2 + c4 * 2]     = h0;
            ((uint32_t*)QsH)[r * S2 + c4 * 2 + 1] = h1;
            ((uint32_t*)QsL)[r * S2 + c4 * 2]     = l0;
            ((uint32_t*)QsL)[r * S2 + c4 * 2 + 1] = l1;
            // K rows are already [n][k] (n = key index, k = d)
            float4 u = *(const float4*)&qkv[((size_t)(b * T + k0t + r)) * (3 * DM) + DM + h * DH + dc + c4 * 4];
            split2(u.x, u.y, h0, l0);
            split2(u.z, u.w, h1, l1);
            ((uint32_t*)KsH)[r * S2 + c4 * 2]     = h0;
            ((uint32_t*)KsH)[r * S2 + c4 * 2 + 1] = h1;
            ((uint32_t*)KsL)[r * S2 + c4 * 2]     = l0;
            ((uint32_t*)KsL)[r * S2 + c4 * 2 + 1] = l1;
        }
        __syncthreads();

#pragma unroll
        for (int ks = 0; ks < 2; ks++) {
            uint32_t aH[4][4], aL[4][4];
#pragma unroll
            for (int i = 0; i < 4; i++) {
                ldA(aH[i], (const uint32_t*)QsH, wm + i * 16, ks * 8, lane);
                ldA(aL[i], (const uint32_t*)QsL, wm + i * 16, ks * 8, lane);
            }
#pragma unroll
            for (int j = 0; j < 4; j++) {
                uint32_t bH[2], bL[2];
                ldB(bH, (const uint32_t*)KsH, wn + j * 8, ks * 8, lane);
                ldB(bL, (const uint32_t*)KsL, wn + j * 8, ks * 8, lane);
#pragma unroll
                for (int i = 0; i < 4; i++) {
                    mma16816(acc[i][j], aH[i], bH);
                    mma16816(acc[i][j], aH[i], bL);
                    mma16816(acc[i][j], aL[i], bH);
                }
            }
        }
        __syncthreads();
    }

    const int r = lane >> 2, c2 = (lane & 3) * 2;
#pragma unroll
    for (int i = 0; i < 4; i++) {
#pragma unroll
        for (int j = 0; j < 4; j++) {
            int ml = wm + i * 16 + r;
            int nl = wn + j * 8 + c2;
            int qg = q0 + ml;
            int kg = k0t + nl;
            float s0 = (kg     <= qg) ? acc[i][j][0] * 0.125f : 0.f;
            float s1 = (kg + 1 <= qg) ? acc[i][j][1] * 0.125f : 0.f;
            *(float2*)&wbase[(size_t)ml * T + nl] = make_float2(s0, s1);
            int qg8 = qg + 8;
            float s2 = (kg     <= qg8) ? acc[i][j][2] * 0.125f : 0.f;
            float s3 = (kg + 1 <= qg8) ? acc[i][j][3] * 0.125f : 0.f;
            *(float2*)&wbase[(size_t)(ml + 8) * T + nl] = make_float2(s2, s3);
        }
    }
}

// ---------------------------------------------------------------------------
// Row softmax stats from stored raw scores. One warp per row.
// ---------------------------------------------------------------------------
__global__ __launch_bounds__(256) void stats_kernel(const float* __restrict__ weights)
{
    const int row = blockIdx.x * 8 + (threadIdx.x >> 5);
    const int lane = threadIdx.x & 31;
    const int q = row & (T - 1);
    const float* wrow = weights + (size_t)row * T;

    float m = ninf(), s = 0.f;
    for (int k = lane; k <= q; k += 32) {
        float x = wrow[k];
        if (x > m) { s = s * __expf(m - x) + 1.0f; m = x; }
        else s += __expf(x - m);
    }
#pragma unroll
    for (int off = 16; off; off >>= 1) {
        float mo = __shfl_xor_sync(0xffffffffu, m, off);
        float so = __shfl_xor_sync(0xffffffffu, s, off);
        float mn = fmaxf(m, mo);
        float e1 = (m == ninf()) ? 0.f : __expf(m - mn);
        float e2 = (mo == ninf()) ? 0.f : __expf(mo - mn);
        s = s * e1 + so * e2;
        m = mn;
    }
    if (lane == 0) {
        g_m[row] = m;
        g_si[row] = 1.0f / s;
    }
}

// ---------------------------------------------------------------------------
// PV: probabilities (in-place into weights) + context = P@V on tensor cores.
// CTA per (128-q tile, h, b). 128 threads, 4 warps (2m x 2n), warp 64x32.
// BM=128 (q), BN=64 (d), BK=32 (keys).
// ---------------------------------------------------------------------------
__global__ __launch_bounds__(128) void pv_tc(float* __restrict__ weights)
{
    const int q0 = blockIdx.x * 128;
    const int h  = blockIdx.y;
    const int b  = blockIdx.z;
    const int bh = b * NH + h;
    const int tid = threadIdx.x, lane = tid & 31, w = tid >> 5;
    const int wm = (w >> 1) * 64, wn = (w & 1) * 32;

    __shared__ __nv_bfloat16 PsH[128 * SK], PsL[128 * SK];
    __shared__ __nv_bfloat16 VsH[64 * SK],  VsL[64 * SK];
    __shared__ float sm_m[128], sm_si[128];

    sm_m[tid]  = g_m [(size_t)bh * T + q0 + tid];
    sm_si[tid] = g_si[(size_t)bh * T + q0 + tid];
    __syncthreads();

    float acc[4][4][4];
#pragma unroll
    for (int i = 0; i < 4; i++)
#pragma unroll
        for (int j = 0; j < 4; j++)
#pragma unroll
            for (int e = 0; e < 4; e++) acc[i][j][e] = 0.f;

    float* wbase = weights + ((size_t)bh * T + q0) * T;
    const float* vbase = g_qkv + (size_t)b * T * (3 * DM) + 2 * DM + h * DH;

    const int nch = (blockIdx.x + 1) * 4;   // 32-key chunks covering k < q0+128
    for (int c = 0; c < nch; c++) {
        const int k0 = c * 32;
        // P tile 128x32: read raw scores, exp-normalize, write back, split to smem
#pragma unroll
        for (int ps = 0; ps < 8; ps++) {
            int g = tid + 128 * ps;
            int r = g >> 3, c4 = g & 7;
            float m = sm_m[r], si = sm_si[r];
            int qg = q0 + r;
            int kg = k0 + c4 * 4;
            float4 v = *(float4*)&wbase[(size_t)r * T + kg];
            float p0 = (kg     <= qg) ? __expf(v.x - m) * si : 0.f;
            float p1 = (kg + 1 <= qg) ? __expf(v.y - m) * si : 0.f;
            float p2 = (kg + 2 <= qg) ? __expf(v.z - m) * si : 0.f;
            float p3 = (kg + 3 <= qg) ? __expf(v.w - m) * si : 0.f;
            *(float4*)&wbase[(size_t)r * T + kg] = make_float4(p0, p1, p2, p3);
            uint32_t h0, l0, h1, l1;
            split2(p0, p1, h0, l0);
            split2(p2, p3, h1, l1);
            ((uint32_t*)PsH)[r * S2 + c4 * 2]     = h0;
            ((uint32_t*)PsH)[r * S2 + c4 * 2 + 1] = h1;
            ((uint32_t*)PsL)[r * S2 + c4 * 2]     = l0;
            ((uint32_t*)PsL)[r * S2 + c4 * 2 + 1] = l1;
        }
        // V tile 32k x 64d -> transposed [n=d][k]
#pragma unroll
        for (int ps = 0; ps < 4; ps++) {
            int g = tid + 128 * ps;
            int vr = g >> 4, c4 = g & 15;
            float4 v = *(const float4*)&vbase[(size_t)(k0 + vr) * (3 * DM) + c4 * 4];
            int n = c4 * 4;
            __nv_bfloat16 hh, ll;
            split1(v.x, hh, ll); VsH[(n + 0) * SK + vr] = hh; VsL[(n + 0) * SK + vr] = ll;
            split1(v.y, hh, ll); VsH[(n + 1) * SK + vr] = hh; VsL[(n + 1) * SK + vr] = ll;
            split1(v.z, hh, ll); VsH[(n + 2) * SK + vr] = hh; VsL[(n + 2) * SK + vr] = ll;
            split1(v.w, hh, ll); VsH[(n + 3) * SK + vr] = hh; VsL[(n + 3) * SK + vr] = ll;
        }
        __syncthreads();

#pragma unroll
        for (int ks = 0; ks < 2; ks++) {
            uint32_t aH[4][4], aL[4][4];
#pragma unroll
            for (int i = 0; i < 4; i++) {
                ldA(aH[i], (const uint32_t*)PsH, wm + i * 16, ks * 8, lane);
                ldA(aL[i], (const uint32_t*)PsL, wm + i * 16, ks * 8, lane);
            }
#pragma unroll
            for (int j = 0; j < 4; j++) {
                uint32_t bH[2], bL[2];
                ldB(bH, (const uint32_t*)VsH, wn + j * 8, ks * 8, lane);
                ldB(bL, (const uint32_t*)VsL, wn + j * 8, ks * 8, lane);
#pragma unroll
                for (int i = 0; i < 4; i++) {
                    mma16816(acc[i][j], aH[i], bH);
                    mma16816(acc[i][j], aH[i], bL);
                    mma16816(acc[i][j], aL[i], bH);
                }
            }
        }
        __syncthreads();
    }

    const int r = lane >> 2, c2 = (lane & 3) * 2;
#pragma unroll
    for (int i = 0; i < 4; i++) {
#pragma unroll
        for (int j = 0; j < 4; j++) {
            int m = q0 + wm + i * 16 + r;
            int n = wn + j * 8 + c2;
            *(float2*)&g_ctx[((size_t)(b * T + m)) * DM + h * DH + n] =
                make_float2(acc[i][j][0], acc[i][j][1]);
            *(float2*)&g_ctx[((size_t)(b * T + m + 8)) * DM + h * DH + n] =
                make_float2(acc[i][j][2], acc[i][j][3]);
        }
    }
}

// ---------------------------------------------------------------------------
extern "C" void kernel_launch(void* const* d_in, const int* in_sizes, int n_in,
                              void* d_out, int out_size)
{
    const float* x     = (const float*)d_in[0];
    const float* w_qkv = (const float*)d_in[1];
    const float* b_qkv = (const float*)d_in[2];
    const float* w_out = (const float*)d_in[3];
    const float* b_out = (const float*)d_in[4];

    float* out     = (float*)d_out;                       // [B,T,DM]
    float* weights = out + (size_t)MROWS * DM;            // [B,H,T,T]

    float *qkv_p, *ctx_p;
    cudaGetSymbolAddress((void**)&qkv_p, g_qkv);
    cudaGetSymbolAddress((void**)&ctx_p, g_ctx);

    // 1) QKV projection
    dim3 g1((3 * DM) / 128, MROWS / 128);
    gemm_bias_tc<<<g1, 256>>>(x, w_qkv, b_qkv, qkv_p, MROWS, 3 * DM, DM);

    // 2) Raw scores -> weights buffer (zeros above the diagonal)
    dim3 g2(T / 128, T / 128, BATCH * NH);
    score_tc<<<g2, 256>>>(weights);

    // 3) Row softmax stats
    stats_kernel<<<BATCH * NH * T / 8, 256>>>(weights);

    // 4) Probabilities (in-place) + context = P@V
    dim3 g4(T / 128, NH, BATCH);
    pv_tc<<<g4, 128>>>(weights);

    // 5) Output projection
    dim3 g5(DM / 128, MROWS / 128);
    gemm_bias_tc<<<g5, 256>>>(ctx_p, w_out, b_out, out, MROWS, DM, DM);
}

// round 6
// speedup vs baseline: 4.7797x; 4.7797x over previous
#include <cuda_runtime.h>
#include <cuda_fp16.h>
#include <cstdint>

// Problem constants
constexpr int BATCH = 4;
constexpr int T     = 2048;
constexpr int NH    = 16;
constexpr int DH    = 64;
constexpr int DM    = 1024;      // NH*DH
constexpr int MROWS = BATCH * T; // 8192
constexpr int QKN   = 3 * DM;    // 3072

constexpr float NEG = -1e30f;    // finite "-inf" (avoids inf-inf NaNs)

// Scratch (device globals; no allocation allowed)
__device__ __half g_xh   [(size_t)MROWS * DM];   // x in fp16 [M][K]
__device__ __half g_wqkvT[(size_t)QKN * DM];     // w_qkv^T fp16 [N][K]
__device__ __half g_woutT[(size_t)DM * DM];      // w_out^T fp16 [N][K]
__device__ __half g_qkvh [(size_t)MROWS * QKN];  // qkv fp16 [M][3072]
__device__ __half g_ctxh [(size_t)MROWS * DM];   // context fp16 [M][DM]

__device__ __forceinline__ void mma16816(float* c, const uint32_t* a, const uint32_t* b) {
    asm volatile(
        "mma.sync.aligned.m16n8k16.row.col.f32.f16.f16.f32 "
        "{%0,%1,%2,%3}, {%4,%5,%6,%7}, {%8,%9}, {%0,%1,%2,%3};\n"
        : "+f"(c[0]), "+f"(c[1]), "+f"(c[2]), "+f"(c[3])
        : "r"(a[0]), "r"(a[1]), "r"(a[2]), "r"(a[3]), "r"(b[0]), "r"(b[1]));
}

__device__ __forceinline__ void ldmx4t(uint32_t r[4], uint32_t saddr) {
    asm volatile(
        "ldmatrix.sync.aligned.m8n8.x4.trans.shared.b16 {%0,%1,%2,%3}, [%4];\n"
        : "=r"(r[0]), "=r"(r[1]), "=r"(r[2]), "=r"(r[3]) : "r"(saddr));
}

__device__ __forceinline__ uint32_t packh2(float a, float b) {
    __half2 h = __floats2half2_rn(a, b);
    return *reinterpret_cast<uint32_t*>(&h);
}

// ---------------------------------------------------------------------------
// Converters
// ---------------------------------------------------------------------------
__global__ void cvt_x_kernel(const float* __restrict__ x, __half* __restrict__ xh, int n8)
{
    int idx = blockIdx.x * blockDim.x + threadIdx.x;
    if (idx >= n8) return;
    const float4* p = (const float4*)(x + (size_t)idx * 8);
    float4 a = p[0], b = p[1];
    __half2 h[4] = { __floats2half2_rn(a.x, a.y), __floats2half2_rn(a.z, a.w),
                     __floats2half2_rn(b.x, b.y), __floats2half2_rn(b.z, b.w) };
    *(uint4*)(xh + (size_t)idx * 8) = *(uint4*)h;
}

// Transpose+convert: w [K=1024][N] fp32 -> wT [N][1024] fp16.
__global__ void cvt_wT_kernel(const float* __restrict__ w, __half* __restrict__ wT, int N)
{
    __shared__ float t[32][33];
    const int k0 = blockIdx.y * 32, n0 = blockIdx.x * 32;
    const int tx = threadIdx.x, ty = threadIdx.y;
#pragma unroll
    for (int i = 0; i < 4; i++)
        t[ty + i * 8][tx] = w[(size_t)(k0 + ty + i * 8) * N + n0 + tx];
    __syncthreads();
#pragma unroll
    for (int i = 0; i < 4; i++)
        wT[(size_t)(n0 + ty + i * 8) * 1024 + k0 + tx] = __float2half(t[tx][ty + i * 8]);
}

// ---------------------------------------------------------------------------
// fp16 GEMM: C[M][N] = A[M][K] @ B^T (B given [N][K], both fp16 k-major) + bias.
// 256 thr, BM=BN=128, BK=64, warps 2m x 4n (warp tile 64x32).
// ---------------------------------------------------------------------------
constexpr int GS = 88;  // smem row stride in halves (176B)

template <bool OUT_HALF>
__global__ __launch_bounds__(256, 2) void gemm_h(
    const __half* __restrict__ A, const __half* __restrict__ B,
    const float* __restrict__ bias, void* __restrict__ Cv,
    int M, int N, int K)
{
    __shared__ alignas(16) __half As[128 * GS];
    __shared__ alignas(16) __half Bs[128 * GS];

    const int tid = threadIdx.x, lane = tid & 31, w = tid >> 5;
    const int row0 = blockIdx.y * 128, col0 = blockIdx.x * 128;
    const int wm = (w & 1) * 64, wn = (w >> 1) * 32;

    float acc[4][4][4];
#pragma unroll
    for (int i = 0; i < 4; i++)
#pragma unroll
        for (int j = 0; j < 4; j++)
#pragma unroll
            for (int e = 0; e < 4; e++) acc[i][j][e] = 0.f;

    const int lr = tid >> 3;
    const int lc = tid & 7;

    for (int k0 = 0; k0 < K; k0 += 64) {
#pragma unroll
        for (int it = 0; it < 4; it++) {
            int r = lr + it * 32;
            *(uint4*)&As[r * GS + lc * 8] =
                *(const uint4*)&A[(size_t)(row0 + r) * K + k0 + lc * 8];
            *(uint4*)&Bs[r * GS + lc * 8] =
                *(const uint4*)&B[(size_t)(col0 + r) * K + k0 + lc * 8];
        }
        __syncthreads();

        const uint32_t* A32 = (const uint32_t*)As;
        const uint32_t* B32 = (const uint32_t*)Bs;
#pragma unroll
        for (int kc = 0; kc < 4; kc++) {
            uint32_t af[4][4];
#pragma unroll
            for (int i = 0; i < 4; i++) {
                const uint32_t* p = A32 + (size_t)(wm + i * 16 + (lane >> 2)) * (GS / 2) + kc * 8 + (lane & 3);
                af[i][0] = p[0];
                af[i][1] = p[8 * (GS / 2)];
                af[i][2] = p[4];
                af[i][3] = p[8 * (GS / 2) + 4];
            }
#pragma unroll
            for (int j = 0; j < 4; j++) {
                uint32_t bf[2];
                const uint32_t* p = B32 + (size_t)(wn + j * 8 + (lane >> 2)) * (GS / 2) + kc * 8 + (lane & 3);
                bf[0] = p[0];
                bf[1] = p[4];
#pragma unroll
                for (int i = 0; i < 4; i++) mma16816(acc[i][j], af[i], bf);
            }
        }
        __syncthreads();
    }

    const int r = lane >> 2, c2 = (lane & 3) * 2;
#pragma unroll
    for (int i = 0; i < 4; i++) {
#pragma unroll
        for (int j = 0; j < 4; j++) {
            int m = row0 + wm + i * 16 + r;
            int n = col0 + wn + j * 8 + c2;
            float b0 = bias[n], b1 = bias[n + 1];
            if (OUT_HALF) {
                __half* C = (__half*)Cv;
                *(uint32_t*)&C[(size_t)m * N + n] = packh2(acc[i][j][0] + b0, acc[i][j][1] + b1);
                *(uint32_t*)&C[(size_t)(m + 8) * N + n] = packh2(acc[i][j][2] + b0, acc[i][j][3] + b1);
            } else {
                float* C = (float*)Cv;
                *(float2*)&C[(size_t)m * N + n] = make_float2(acc[i][j][0] + b0, acc[i][j][1] + b1);
                *(float2*)&C[(size_t)(m + 8) * N + n] = make_float2(acc[i][j][2] + b0, acc[i][j][3] + b1);
            }
        }
    }
}

// ---------------------------------------------------------------------------
// Fused attention: per CTA = (64-q tile, head, batch). 128 thr, 4 warps.
// Warp grid 2m x 2n over a 64q x 128k score tile (warp tile 32q x 64k).
// ---------------------------------------------------------------------------
__global__ __launch_bounds__(128, 2) void attn_fused(
    const __half* __restrict__ qkvh, float* __restrict__ weights,
    __half* __restrict__ ctxh)
{
    __shared__ alignas(16) __half Ks[128 * GS];   // K tile [key][d]
    __shared__ alignas(16) __half Vn[128 * GS];   // V tile [key][d] / ctx overlay
    __shared__ float redm[128], reds[128];
    __shared__ float sm_m[64], sm_si[64];

    const int qi = 31 - blockIdx.x;       // heavy tiles first
    const int q0 = qi * 64;
    const int h  = blockIdx.y;
    const int b  = blockIdx.z;
    const int bh = b * NH + h;
    const int tid = threadIdx.x, lane = tid & 31, w = tid >> 5;
    const int wm = (w & 1) * 32;
    const int wn = (w >> 1) * 64;

    const int nkt = ((q0 + 63) >> 7) + 1;

    // ---- Q fragments (persist in regs) ----
    uint32_t qa[2][4][4];
#pragma unroll
    for (int i = 0; i < 2; i++) {
        const __half* qr0 = qkvh + ((size_t)(b * T + q0 + wm + i * 16 + (lane >> 2))) * QKN
                            + h * DH + (lane & 3) * 2;
        const __half* qr8 = qr0 + (size_t)8 * QKN;
#pragma unroll
        for (int kc = 0; kc < 4; kc++) {
            qa[i][kc][0] = *(const uint32_t*)(qr0 + kc * 16);
            qa[i][kc][1] = *(const uint32_t*)(qr8 + kc * 16);
            qa[i][kc][2] = *(const uint32_t*)(qr0 + kc * 16 + 8);
            qa[i][kc][3] = *(const uint32_t*)(qr8 + kc * 16 + 8);
        }
    }

    const __half* kbase = qkvh + (size_t)b * T * QKN + DM + h * DH;
    const __half* vbase = qkvh + (size_t)b * T * QKN + 2 * DM + h * DH;

    float rm[4], rs[4];
#pragma unroll
    for (int t = 0; t < 4; t++) { rm[t] = NEG; rs[t] = 0.f; }

    const int lr = tid >> 3, lc = tid & 7;

    // =========================== PASS 1 ===========================
    for (int kt = 0; kt < nkt; kt++) {
        __syncthreads();
#pragma unroll
        for (int it = 0; it < 8; it++) {
            int r = lr + it * 16;
            *(uint4*)&Ks[r * GS + lc * 8] =
                *(const uint4*)&kbase[(size_t)(kt * 128 + r) * QKN + lc * 8];
        }
        __syncthreads();

        float acc[2][8][4];
#pragma unroll
        for (int i = 0; i < 2; i++)
#pragma unroll
            for (int j = 0; j < 8; j++)
#pragma unroll
                for (int e = 0; e < 4; e++) acc[i][j][e] = 0.f;

        const uint32_t* K32 = (const uint32_t*)Ks;
#pragma unroll
        for (int kc = 0; kc < 4; kc++) {
#pragma unroll
            for (int j = 0; j < 8; j++) {
                uint32_t bf[2];
                const uint32_t* p = K32 + (size_t)(wn + j * 8 + (lane >> 2)) * (GS / 2) + kc * 8 + (lane & 3);
                bf[0] = p[0];
                bf[1] = p[4];
                mma16816(acc[0][j], qa[0][kc], bf);
                mma16816(acc[1][j], qa[1][kc], bf);
            }
        }

        const bool mk = (kt * 128 + 127 > q0);
#pragma unroll
        for (int i = 0; i < 2; i++) {
#pragma unroll
            for (int rv = 0; rv < 2; rv++) {
                const int t = i * 2 + rv;
                const int qg = q0 + wm + i * 16 + (lane >> 2) + rv * 8;
                float tmax = NEG;
#pragma unroll
                for (int j = 0; j < 8; j++) {
#pragma unroll
                    for (int e = 0; e < 2; e++) {
                        int kg = kt * 128 + wn + j * 8 + (lane & 3) * 2 + e;
                        float v = acc[i][j][rv * 2 + e] * 0.125f;
                        if (mk && kg > qg) v = NEG;
                        acc[i][j][rv * 2 + e] = v;
                        tmax = fmaxf(tmax, v);
                    }
                }
                tmax = fmaxf(tmax, __shfl_xor_sync(0xffffffffu, tmax, 1));
                tmax = fmaxf(tmax, __shfl_xor_sync(0xffffffffu, tmax, 2));
                float mnew = fmaxf(rm[t], tmax);
                float ssum = 0.f;
#pragma unroll
                for (int j = 0; j < 8; j++)
#pragma unroll
                    for (int e = 0; e < 2; e++)
                        ssum += __expf(acc[i][j][rv * 2 + e] - mnew);   // finite args
                ssum += __shfl_xor_sync(0xffffffffu, ssum, 1);
                ssum += __shfl_xor_sync(0xffffffffu, ssum, 2);
                rs[t] = rs[t] * __expf(rm[t] - mnew) + ssum;
                rm[t] = mnew;
            }
        }
    }

    // ---- merge stats across the two key-half warps ----
    __syncthreads();
    if ((lane & 3) == 0) {
        const int slot = wn >> 6;
#pragma unroll
        for (int i = 0; i < 2; i++)
#pragma unroll
            for (int rv = 0; rv < 2; rv++) {
                int row = wm + i * 16 + (lane >> 2) + rv * 8;
                redm[row * 2 + slot] = rm[i * 2 + rv];
                reds[row * 2 + slot] = rs[i * 2 + rv];
            }
    }
    __syncthreads();
    if (tid < 64) {
        float m0 = redm[tid * 2], m1 = redm[tid * 2 + 1];
        float s0 = reds[tid * 2], s1 = reds[tid * 2 + 1];
        float mm = fmaxf(m0, m1);
        float ss = s0 * __expf(m0 - mm) + s1 * __expf(m1 - mm);
        sm_m[tid] = mm;
        sm_si[tid] = 1.0f / ss;
    }
    __syncthreads();

    float fm[4], fsi[4];
#pragma unroll
    for (int i = 0; i < 2; i++)
#pragma unroll
        for (int rv = 0; rv < 2; rv++) {
            int row = wm + i * 16 + (lane >> 2) + rv * 8;
            fm[i * 2 + rv] = sm_m[row];
            fsi[i * 2 + rv] = sm_si[row];
        }

    float ctx[2][8][4];
#pragma unroll
    for (int i = 0; i < 2; i++)
#pragma unroll
        for (int j = 0; j < 8; j++)
#pragma unroll
            for (int e = 0; e < 4; e++) ctx[i][j][e] = 0.f;

    const int vlo = (lane & 15) * GS + (lane >> 4) * 8;
    uint32_t vsbase = (uint32_t)__cvta_generic_to_shared(Vn);

    // =========================== PASS 2 ===========================
    for (int kt = 0; kt < nkt; kt++) {
        __syncthreads();
#pragma unroll
        for (int it = 0; it < 8; it++) {
            int r = lr + it * 16;
            *(uint4*)&Ks[r * GS + lc * 8] =
                *(const uint4*)&kbase[(size_t)(kt * 128 + r) * QKN + lc * 8];
            *(uint4*)&Vn[r * GS + lc * 8] =
                *(const uint4*)&vbase[(size_t)(kt * 128 + r) * QKN + lc * 8];
        }
        __syncthreads();

        float acc[2][8][4];
#pragma unroll
        for (int i = 0; i < 2; i++)
#pragma unroll
            for (int j = 0; j < 8; j++)
#pragma unroll
                for (int e = 0; e < 4; e++) acc[i][j][e] = 0.f;

        const uint32_t* K32 = (const uint32_t*)Ks;
#pragma unroll
        for (int kc = 0; kc < 4; kc++) {
#pragma unroll
            for (int j = 0; j < 8; j++) {
                uint32_t bf[2];
                const uint32_t* p = K32 + (size_t)(wn + j * 8 + (lane >> 2)) * (GS / 2) + kc * 8 + (lane & 3);
                bf[0] = p[0];
                bf[1] = p[4];
                mma16816(acc[0][j], qa[0][kc], bf);
                mma16816(acc[1][j], qa[1][kc], bf);
            }
        }

        const bool mk = (kt * 128 + 127 > q0);
#pragma unroll
        for (int i = 0; i < 2; i++) {
#pragma unroll
            for (int rv = 0; rv < 2; rv++) {
                const int t = i * 2 + rv;
                const int qg = q0 + wm + i * 16 + (lane >> 2) + rv * 8;
                float m = fm[t], si = fsi[t];
                float* wrow = weights + ((size_t)bh * T + qg) * T + kt * 128 + wn + (lane & 3) * 2;
#pragma unroll
                for (int j = 0; j < 8; j++) {
                    int kg = kt * 128 + wn + j * 8 + (lane & 3) * 2;
                    float v0 = acc[i][j][rv * 2 + 0] * 0.125f;
                    float v1 = acc[i][j][rv * 2 + 1] * 0.125f;
                    float p0 = (mk && kg > qg)     ? 0.f : __expf(v0 - m) * si;
                    float p1 = (mk && kg + 1 > qg) ? 0.f : __expf(v1 - m) * si;
                    acc[i][j][rv * 2 + 0] = p0;
                    acc[i][j][rv * 2 + 1] = p1;
                    *(float2*)&wrow[j * 8] = make_float2(p0, p1);
                }
            }
        }

        // PV: P fragments straight from acc; V via ldmatrix.trans
#pragma unroll
        for (int kc = 0; kc < 4; kc++) {
            uint32_t pa[2][4];
#pragma unroll
            for (int i = 0; i < 2; i++) {
                pa[i][0] = packh2(acc[i][2 * kc][0],     acc[i][2 * kc][1]);
                pa[i][1] = packh2(acc[i][2 * kc][2],     acc[i][2 * kc][3]);
                pa[i][2] = packh2(acc[i][2 * kc + 1][0], acc[i][2 * kc + 1][1]);
                pa[i][3] = packh2(acc[i][2 * kc + 1][2], acc[i][2 * kc + 1][3]);
            }
#pragma unroll
            for (int njp = 0; njp < 4; njp++) {
                uint32_t vf[4];
                uint32_t addr = vsbase + (uint32_t)((wn + kc * 16) * GS + njp * 16 + vlo) * 2;
                ldmx4t(vf, addr);
#pragma unroll
                for (int i = 0; i < 2; i++) {
                    mma16816(ctx[i][2 * njp],     pa[i], vf);
                    mma16816(ctx[i][2 * njp + 1], pa[i], vf + 2);
                }
            }
        }
    }

    // ---- reduce ctx across the two key-half warps, write fp16 ----
    __syncthreads();
    float* cb = (float*)Vn;
    if (wn == 0) {
#pragma unroll
        for (int i = 0; i < 2; i++)
#pragma unroll
            for (int j = 0; j < 8; j++) {
                int row = wm + i * 16 + (lane >> 2);
                int d = j * 8 + (lane & 3) * 2;
                cb[row * 68 + d]       = ctx[i][j][0];
                cb[row * 68 + d + 1]   = ctx[i][j][1];
                cb[(row + 8) * 68 + d]     = ctx[i][j][2];
                cb[(row + 8) * 68 + d + 1] = ctx[i][j][3];
            }
    }
    __syncthreads();
    if (wn == 64) {
#pragma unroll
        for (int i = 0; i < 2; i++)
#pragma unroll
            for (int j = 0; j < 8; j++) {
                int row = wm + i * 16 + (lane >> 2);
                int d = j * 8 + (lane & 3) * 2;
                cb[row * 68 + d]       += ctx[i][j][0];
                cb[row * 68 + d + 1]   += ctx[i][j][1];
                cb[(row + 8) * 68 + d]     += ctx[i][j][2];
                cb[(row + 8) * 68 + d + 1] += ctx[i][j][3];
            }
    }
    __syncthreads();
#pragma unroll
    for (int it = 0; it < 16; it++) {
        int idx = tid + it * 128;
        int row = idx >> 5, d2 = (idx & 31) * 2;
        uint32_t hv = packh2(cb[row * 68 + d2], cb[row * 68 + d2 + 1]);
        *(uint32_t*)&ctxh[((size_t)(b * T + q0 + row)) * DM + h * DH + d2] = hv;
    }

    // ---- zero-fill strictly-future weight columns ----
    const int c0 = nkt * 128;
    if (c0 < T) {
        const int cpr = (T - c0) >> 2;
        float4 z = make_float4(0.f, 0.f, 0.f, 0.f);
        for (int idx = tid; idx < 64 * cpr; idx += 128) {
            int row = idx / cpr, c = idx % cpr;
            *(float4*)&weights[((size_t)bh * T + q0 + row) * T + c0 + c * 4] = z;
        }
    }
}

// ---------------------------------------------------------------------------
extern "C" void kernel_launch(void* const* d_in, const int* in_sizes, int n_in,
                              void* d_out, int out_size)
{
    const float* x     = (const float*)d_in[0];
    const float* w_qkv = (const float*)d_in[1];
    const float* b_qkv = (const float*)d_in[2];
    const float* w_out = (const float*)d_in[3];
    const float* b_out = (const float*)d_in[4];

    float* out     = (float*)d_out;               // [B,T,DM] fp32
    float* weights = out + (size_t)MROWS * DM;    // [B,H,T,T] fp32

    __half *xh, *wqkvT, *woutT, *qkvh, *ctxh;
    cudaGetSymbolAddress((void**)&xh,    g_xh);
    cudaGetSymbolAddress((void**)&wqkvT, g_wqkvT);
    cudaGetSymbolAddress((void**)&woutT, g_woutT);
    cudaGetSymbolAddress((void**)&qkvh,  g_qkvh);
    cudaGetSymbolAddress((void**)&ctxh,  g_ctxh);

    // 0) fp16 conversions
    cvt_x_kernel<<<(MROWS * DM / 8 + 255) / 256, 256>>>(x, xh, MROWS * DM / 8);
    cvt_wT_kernel<<<dim3(QKN / 32, DM / 32), dim3(32, 8)>>>(w_qkv, wqkvT, QKN);
    cvt_wT_kernel<<<dim3(DM / 32, DM / 32), dim3(32, 8)>>>(w_out, woutT, DM);

    // 1) QKV projection (fp16 out)
    dim3 g1(QKN / 128, MROWS / 128);
    gemm_h<true><<<g1, 256>>>(xh, wqkvT, b_qkv, qkvh, MROWS, QKN, DM);

    // 2) Fused attention: weights (fp32, normalized, zero-filled) + ctx fp16
    dim3 g2(T / 64, NH, BATCH);
    attn_fused<<<g2, 128>>>(qkvh, weights, ctxh);

    // 3) Output projection (fp32 out)
    dim3 g3(DM / 128, MROWS / 128);
    gemm_h<false><<<g3, 256>>>(ctxh, woutT, b_out, out, MROWS, DM, DM);
}

// round 7
// speedup vs baseline: 5.5151x; 1.1539x over previous
#include <cuda_runtime.h>
#include <cuda_fp16.h>
#include <cstdint>

// Problem constants
constexpr int BATCH = 4;
constexpr int T     = 2048;
constexpr int NH    = 16;
constexpr int DH    = 64;
constexpr int DM    = 1024;      // NH*DH
constexpr int MROWS = BATCH * T; // 8192
constexpr int QKN   = 3 * DM;    // 3072

constexpr float NEG = -1e30f;                    // finite "-inf"
constexpr float SC  = 0.18033688011112042f;      // 0.125 * log2(e)

constexpr int GS   = 72;          // smem row stride in halves (144 B)
constexpr int TILE = 128 * GS;    // halves per 128-row tile buffer

// Scratch (device globals; no allocation allowed)
__device__ __half g_xh   [(size_t)MROWS * DM];
__device__ __half g_wqkvT[(size_t)QKN * DM];
__device__ __half g_woutT[(size_t)DM * DM];
__device__ __half g_qkvh [(size_t)MROWS * QKN];
__device__ __half g_ctxh [(size_t)MROWS * DM];

__device__ __forceinline__ void mma16816(float* c, const uint32_t* a, const uint32_t* b) {
    asm volatile(
        "mma.sync.aligned.m16n8k16.row.col.f32.f16.f16.f32 "
        "{%0,%1,%2,%3}, {%4,%5,%6,%7}, {%8,%9}, {%0,%1,%2,%3};\n"
        : "+f"(c[0]), "+f"(c[1]), "+f"(c[2]), "+f"(c[3])
        : "r"(a[0]), "r"(a[1]), "r"(a[2]), "r"(a[3]), "r"(b[0]), "r"(b[1]));
}
__device__ __forceinline__ void ldmx4(uint32_t r[4], uint32_t saddr) {
    asm volatile("ldmatrix.sync.aligned.m8n8.x4.shared.b16 {%0,%1,%2,%3}, [%4];\n"
        : "=r"(r[0]), "=r"(r[1]), "=r"(r[2]), "=r"(r[3]) : "r"(saddr));
}
__device__ __forceinline__ void ldmx4t(uint32_t r[4], uint32_t saddr) {
    asm volatile("ldmatrix.sync.aligned.m8n8.x4.trans.shared.b16 {%0,%1,%2,%3}, [%4];\n"
        : "=r"(r[0]), "=r"(r[1]), "=r"(r[2]), "=r"(r[3]) : "r"(saddr));
}
__device__ __forceinline__ uint32_t packh2(float a, float b) {
    __half2 h = __floats2half2_rn(a, b);
    return *reinterpret_cast<uint32_t*>(&h);
}
__device__ __forceinline__ float ex2(float x) {
    float y; asm("ex2.approx.f32 %0, %1;" : "=f"(y) : "f"(x)); return y;
}
__device__ __forceinline__ void cpa16(uint32_t s, const void* g) {
    asm volatile("cp.async.cg.shared.global [%0], [%1], 16;\n" :: "r"(s), "l"(g));
}
__device__ __forceinline__ void cpcommit() { asm volatile("cp.async.commit_group;\n"); }
__device__ __forceinline__ void cpwait0()  { asm volatile("cp.async.wait_group 0;\n"); }

// ---------------------------------------------------------------------------
// Converters
// ---------------------------------------------------------------------------
__global__ void cvt_x_kernel(const float* __restrict__ x, __half* __restrict__ xh, int n8)
{
    int idx = blockIdx.x * blockDim.x + threadIdx.x;
    if (idx >= n8) return;
    const float4* p = (const float4*)(x + (size_t)idx * 8);
    float4 a = p[0], b = p[1];
    __half2 h[4] = { __floats2half2_rn(a.x, a.y), __floats2half2_rn(a.z, a.w),
                     __floats2half2_rn(b.x, b.y), __floats2half2_rn(b.z, b.w) };
    *(uint4*)(xh + (size_t)idx * 8) = *(uint4*)h;
}

__global__ void cvt_wT_kernel(const float* __restrict__ w, __half* __restrict__ wT, int N)
{
    __shared__ float t[32][33];
    const int k0 = blockIdx.y * 32, n0 = blockIdx.x * 32;
    const int tx = threadIdx.x, ty = threadIdx.y;
#pragma unroll
    for (int i = 0; i < 4; i++)
        t[ty + i * 8][tx] = w[(size_t)(k0 + ty + i * 8) * N + n0 + tx];
    __syncthreads();
#pragma unroll
    for (int i = 0; i < 4; i++)
        wT[(size_t)(n0 + ty + i * 8) * 1024 + k0 + tx] = __float2half(t[tx][ty + i * 8]);
}

// ---------------------------------------------------------------------------
// fp16 GEMM: C = A[M][K] @ B^T + bias, B given [N][K]. 256 thr, BM=BN=128,
// BK=64, 2-stage cp.async pipeline, ldmatrix fragments.
// Dynamic smem: 4 * TILE halves (A0,A1,B0,B1).
// ---------------------------------------------------------------------------
template <bool OUT_HALF>
__global__ __launch_bounds__(256, 2) void gemm_h(
    const __half* __restrict__ A, const __half* __restrict__ B,
    const float* __restrict__ bias, void* __restrict__ Cv,
    int M, int N, int K)
{
    extern __shared__ __half smraw[];
    const int tid = threadIdx.x, lane = tid & 31, w = tid >> 5;
    const int row0 = blockIdx.y * 128, col0 = blockIdx.x * 128;
    const int wm = (w & 1) * 64, wn = (w >> 1) * 32;
    const uint32_t sb = (uint32_t)__cvta_generic_to_shared(smraw);

    float acc[4][4][4];
#pragma unroll
    for (int i = 0; i < 4; i++)
#pragma unroll
        for (int j = 0; j < 4; j++)
#pragma unroll
            for (int e = 0; e < 4; e++) acc[i][j][e] = 0.f;

    const int lr = tid >> 3, lc = tid & 7;
    // ldmatrix lane address components
    const int arow = wm + (lane & 7) + ((lane & 8) ? 8 : 0);
    const int acol = (lane >> 4) * 8;
    const int brow = wn + (lane & 7) + ((lane & 16) ? 8 : 0);
    const int bcol = ((lane >> 3) & 1) * 8;

    // prefetch k-chunk 0 into stage 0
#pragma unroll
    for (int it = 0; it < 4; it++) {
        int r = lr + it * 32;
        cpa16(sb + (uint32_t)(0 * TILE + r * GS + lc * 8) * 2, &A[(size_t)(row0 + r) * K + lc * 8]);
        cpa16(sb + (uint32_t)(2 * TILE + r * GS + lc * 8) * 2, &B[(size_t)(col0 + r) * K + lc * 8]);
    }
    cpcommit();

    const int KT = K >> 6;
    for (int kt = 0; kt < KT; kt++) {
        cpwait0();
        __syncthreads();
        if (kt + 1 < KT) {
            const int k0 = (kt + 1) * 64, st = (kt + 1) & 1;
#pragma unroll
            for (int it = 0; it < 4; it++) {
                int r = lr + it * 32;
                cpa16(sb + (uint32_t)(st * TILE + r * GS + lc * 8) * 2,
                      &A[(size_t)(row0 + r) * K + k0 + lc * 8]);
                cpa16(sb + (uint32_t)((2 + st) * TILE + r * GS + lc * 8) * 2,
                      &B[(size_t)(col0 + r) * K + k0 + lc * 8]);
            }
            cpcommit();
        }
        const int st = kt & 1;
        const uint32_t sA = sb + (uint32_t)(st * TILE) * 2;
        const uint32_t sB = sb + (uint32_t)((2 + st) * TILE) * 2;
#pragma unroll
        for (int kc = 0; kc < 4; kc++) {
            uint32_t af[4][4];
#pragma unroll
            for (int i = 0; i < 4; i++)
                ldmx4(af[i], sA + (uint32_t)((arow + i * 16) * GS + kc * 16 + acol) * 2);
#pragma unroll
            for (int jp = 0; jp < 2; jp++) {
                uint32_t bf[4];
                ldmx4(bf, sB + (uint32_t)((brow + jp * 16) * GS + kc * 16 + bcol) * 2);
#pragma unroll
                for (int i = 0; i < 4; i++) {
                    mma16816(acc[i][2 * jp],     af[i], bf);
                    mma16816(acc[i][2 * jp + 1], af[i], bf + 2);
                }
            }
        }
    }

    const int r = lane >> 2, c2 = (lane & 3) * 2;
#pragma unroll
    for (int i = 0; i < 4; i++) {
#pragma unroll
        for (int j = 0; j < 4; j++) {
            int m = row0 + wm + i * 16 + r;
            int n = col0 + wn + j * 8 + c2;
            float b0 = bias[n], b1 = bias[n + 1];
            if (OUT_HALF) {
                __half* C = (__half*)Cv;
                *(uint32_t*)&C[(size_t)m * N + n] = packh2(acc[i][j][0] + b0, acc[i][j][1] + b1);
                *(uint32_t*)&C[(size_t)(m + 8) * N + n] = packh2(acc[i][j][2] + b0, acc[i][j][3] + b1);
            } else {
                float* C = (float*)Cv;
                *(float2*)&C[(size_t)m * N + n] = make_float2(acc[i][j][0] + b0, acc[i][j][1] + b1);
                *(float2*)&C[(size_t)(m + 8) * N + n] = make_float2(acc[i][j][2] + b0, acc[i][j][3] + b1);
            }
        }
    }
}

// ---------------------------------------------------------------------------
// Fused attention. CTA = (64-q tile, head, batch), 128 thr, 4 warps (2m x 2n).
// Dynamic smem: K stages [0,1], V stages [2,3] (each TILE halves).
// ---------------------------------------------------------------------------
__global__ __launch_bounds__(128, 2) void attn_fused(
    const __half* __restrict__ qkvh, float* __restrict__ weights,
    __half* __restrict__ ctxh)
{
    extern __shared__ __half smraw[];
    __shared__ float redm[128], reds[128];
    __shared__ float sm_m[64], sm_si[64];

    const int qi = 31 - blockIdx.x;       // heavy tiles first
    const int q0 = qi * 64;
    const int h  = blockIdx.y;
    const int b  = blockIdx.z;
    const int bh = b * NH + h;
    const int tid = threadIdx.x, lane = tid & 31, w = tid >> 5;
    const int wm = (w & 1) * 32;
    const int wn = (w >> 1) * 64;
    const uint32_t sb = (uint32_t)__cvta_generic_to_shared(smraw);

    const int nkt = ((q0 + 63) >> 7) + 1;

    // ---- Q fragments (persist in regs) ----
    uint32_t qa[2][4][4];
#pragma unroll
    for (int i = 0; i < 2; i++) {
        const __half* qr0 = qkvh + ((size_t)(b * T + q0 + wm + i * 16 + (lane >> 2))) * QKN
                            + h * DH + (lane & 3) * 2;
        const __half* qr8 = qr0 + (size_t)8 * QKN;
#pragma unroll
        for (int kc = 0; kc < 4; kc++) {
            qa[i][kc][0] = *(const uint32_t*)(qr0 + kc * 16);
            qa[i][kc][1] = *(const uint32_t*)(qr8 + kc * 16);
            qa[i][kc][2] = *(const uint32_t*)(qr0 + kc * 16 + 8);
            qa[i][kc][3] = *(const uint32_t*)(qr8 + kc * 16 + 8);
        }
    }

    const __half* kbase = qkvh + (size_t)b * T * QKN + DM + h * DH;
    const __half* vbase = qkvh + (size_t)b * T * QKN + 2 * DM + h * DH;

    const int lr = tid >> 3, lc = tid & 7;
    const int brow = wn + (lane & 7) + ((lane & 16) ? 8 : 0);
    const int bcol = ((lane >> 3) & 1) * 8;
    const int vlo  = (lane & 15) * GS + (lane >> 4) * 8;

    float rm[4], rs[4];
#pragma unroll
    for (int t = 0; t < 4; t++) { rm[t] = NEG; rs[t] = 0.f; }

    // =========================== PASS 1 ===========================
#pragma unroll
    for (int it = 0; it < 8; it++) {
        int r = lr + it * 16;
        cpa16(sb + (uint32_t)(0 * TILE + r * GS + lc * 8) * 2, &kbase[(size_t)r * QKN + lc * 8]);
    }
    cpcommit();

    for (int kt = 0; kt < nkt; kt++) {
        cpwait0();
        __syncthreads();
        if (kt + 1 < nkt) {
            const int st = (kt + 1) & 1;
#pragma unroll
            for (int it = 0; it < 8; it++) {
                int r = lr + it * 16;
                cpa16(sb + (uint32_t)(st * TILE + r * GS + lc * 8) * 2,
                      &kbase[(size_t)((kt + 1) * 128 + r) * QKN + lc * 8]);
            }
            cpcommit();
        }
        const uint32_t sK = sb + (uint32_t)((kt & 1) * TILE) * 2;

        float acc[2][8][4];
#pragma unroll
        for (int i = 0; i < 2; i++)
#pragma unroll
            for (int j = 0; j < 8; j++)
#pragma unroll
                for (int e = 0; e < 4; e++) acc[i][j][e] = 0.f;

#pragma unroll
        for (int kc = 0; kc < 4; kc++) {
#pragma unroll
            for (int jp = 0; jp < 4; jp++) {
                uint32_t bf[4];
                ldmx4(bf, sK + (uint32_t)((brow + jp * 16) * GS + kc * 16 + bcol) * 2);
                mma16816(acc[0][2 * jp],     qa[0][kc], bf);
                mma16816(acc[0][2 * jp + 1], qa[0][kc], bf + 2);
                mma16816(acc[1][2 * jp],     qa[1][kc], bf);
                mma16816(acc[1][2 * jp + 1], qa[1][kc], bf + 2);
            }
        }

        const bool mk = (kt * 128 + 127 > q0);
#pragma unroll
        for (int i = 0; i < 2; i++) {
#pragma unroll
            for (int rv = 0; rv < 2; rv++) {
                const int t = i * 2 + rv;
                const int qg = q0 + wm + i * 16 + (lane >> 2) + rv * 8;
                float tmax = NEG;
#pragma unroll
                for (int j = 0; j < 8; j++) {
#pragma unroll
                    for (int e = 0; e < 2; e++) {
                        int kg = kt * 128 + wn + j * 8 + (lane & 3) * 2 + e;
                        float v = acc[i][j][rv * 2 + e] * SC;     // log2 domain
                        if (mk && kg > qg) v = NEG;
                        acc[i][j][rv * 2 + e] = v;
                        tmax = fmaxf(tmax, v);
                    }
                }
                tmax = fmaxf(tmax, __shfl_xor_sync(0xffffffffu, tmax, 1));
                tmax = fmaxf(tmax, __shfl_xor_sync(0xffffffffu, tmax, 2));
                float mnew = fmaxf(rm[t], tmax);
                float ssum = 0.f;
#pragma unroll
                for (int j = 0; j < 8; j++)
#pragma unroll
                    for (int e = 0; e < 2; e++)
                        ssum += ex2(acc[i][j][rv * 2 + e] - mnew);
                ssum += __shfl_xor_sync(0xffffffffu, ssum, 1);
                ssum += __shfl_xor_sync(0xffffffffu, ssum, 2);
                rs[t] = rs[t] * ex2(rm[t] - mnew) + ssum;
                rm[t] = mnew;
            }
        }
    }

    // ---- merge stats across the two key-half warps ----
    __syncthreads();
    if ((lane & 3) == 0) {
        const int slot = wn >> 6;
#pragma unroll
        for (int i = 0; i < 2; i++)
#pragma unroll
            for (int rv = 0; rv < 2; rv++) {
                int row = wm + i * 16 + (lane >> 2) + rv * 8;
                redm[row * 2 + slot] = rm[i * 2 + rv];
                reds[row * 2 + slot] = rs[i * 2 + rv];
            }
    }
    __syncthreads();
    if (tid < 64) {
        float m0 = redm[tid * 2], m1 = redm[tid * 2 + 1];
        float s0 = reds[tid * 2], s1 = reds[tid * 2 + 1];
        float mm = fmaxf(m0, m1);
        float ss = s0 * ex2(m0 - mm) + s1 * ex2(m1 - mm);
        sm_m[tid] = mm;
        sm_si[tid] = 1.0f / ss;
    }
    __syncthreads();

    float fm[4], fsi[4];
#pragma unroll
    for (int i = 0; i < 2; i++)
#pragma unroll
        for (int rv = 0; rv < 2; rv++) {
            int row = wm + i * 16 + (lane >> 2) + rv * 8;
            fm[i * 2 + rv] = sm_m[row];
            fsi[i * 2 + rv] = sm_si[row];
        }

    float ctx[2][8][4];
#pragma unroll
    for (int i = 0; i < 2; i++)
#pragma unroll
        for (int j = 0; j < 8; j++)
#pragma unroll
            for (int e = 0; e < 4; e++) ctx[i][j][e] = 0.f;

    // =========================== PASS 2 ===========================
#pragma unroll
    for (int it = 0; it < 8; it++) {
        int r = lr + it * 16;
        cpa16(sb + (uint32_t)(0 * TILE + r * GS + lc * 8) * 2, &kbase[(size_t)r * QKN + lc * 8]);
        cpa16(sb + (uint32_t)(2 * TILE + r * GS + lc * 8) * 2, &vbase[(size_t)r * QKN + lc * 8]);
    }
    cpcommit();

    for (int kt = 0; kt < nkt; kt++) {
        cpwait0();
        __syncthreads();
        if (kt + 1 < nkt) {
            const int st = (kt + 1) & 1;
#pragma unroll
            for (int it = 0; it < 8; it++) {
                int r = lr + it * 16;
                cpa16(sb + (uint32_t)(st * TILE + r * GS + lc * 8) * 2,
                      &kbase[(size_t)((kt + 1) * 128 + r) * QKN + lc * 8]);
                cpa16(sb + (uint32_t)((2 + st) * TILE + r * GS + lc * 8) * 2,
                      &vbase[(size_t)((kt + 1) * 128 + r) * QKN + lc * 8]);
            }
            cpcommit();
        }
        const uint32_t sK = sb + (uint32_t)((kt & 1) * TILE) * 2;
        const uint32_t sV = sb + (uint32_t)((2 + (kt & 1)) * TILE) * 2;

        float acc[2][8][4];
#pragma unroll
        for (int i = 0; i < 2; i++)
#pragma unroll
            for (int j = 0; j < 8; j++)
#pragma unroll
                for (int e = 0; e < 4; e++) acc[i][j][e] = 0.f;

#pragma unroll
        for (int kc = 0; kc < 4; kc++) {
#pragma unroll
            for (int jp = 0; jp < 4; jp++) {
                uint32_t bf[4];
                ldmx4(bf, sK + (uint32_t)((brow + jp * 16) * GS + kc * 16 + bcol) * 2);
                mma16816(acc[0][2 * jp],     qa[0][kc], bf);
                mma16816(acc[0][2 * jp + 1], qa[0][kc], bf + 2);
                mma16816(acc[1][2 * jp],     qa[1][kc], bf);
                mma16816(acc[1][2 * jp + 1], qa[1][kc], bf + 2);
            }
        }

        const bool mk = (kt * 128 + 127 > q0);
#pragma unroll
        for (int i = 0; i < 2; i++) {
#pragma unroll
            for (int rv = 0; rv < 2; rv++) {
                const int t = i * 2 + rv;
                const int qg = q0 + wm + i * 16 + (lane >> 2) + rv * 8;
                float m = fm[t], si = fsi[t];
                float* wrow = weights + ((size_t)bh * T + qg) * T + kt * 128 + wn + (lane & 3) * 2;
#pragma unroll
                for (int j = 0; j < 8; j++) {
                    int kg = kt * 128 + wn + j * 8 + (lane & 3) * 2;
                    float v0 = acc[i][j][rv * 2 + 0] * SC;
                    float v1 = acc[i][j][rv * 2 + 1] * SC;
                    float p0 = (mk && kg > qg)     ? 0.f : ex2(v0 - m) * si;
                    float p1 = (mk && kg + 1 > qg) ? 0.f : ex2(v1 - m) * si;
                    acc[i][j][rv * 2 + 0] = p0;
                    acc[i][j][rv * 2 + 1] = p1;
                    *(float2*)&wrow[j * 8] = make_float2(p0, p1);
                }
            }
        }

        // PV: P from accumulators; V via ldmatrix.trans
#pragma unroll
        for (int kc = 0; kc < 4; kc++) {
            uint32_t pa[2][4];
#pragma unroll
            for (int i = 0; i < 2; i++) {
                pa[i][0] = packh2(acc[i][2 * kc][0],     acc[i][2 * kc][1]);
                pa[i][1] = packh2(acc[i][2 * kc][2],     acc[i][2 * kc][3]);
                pa[i][2] = packh2(acc[i][2 * kc + 1][0], acc[i][2 * kc + 1][1]);
                pa[i][3] = packh2(acc[i][2 * kc + 1][2], acc[i][2 * kc + 1][3]);
            }
#pragma unroll
            for (int njp = 0; njp < 4; njp++) {
                uint32_t vf[4];
                ldmx4t(vf, sV + (uint32_t)((wn + kc * 16) * GS + njp * 16 + vlo) * 2);
#pragma unroll
                for (int i = 0; i < 2; i++) {
                    mma16816(ctx[i][2 * njp],     pa[i], vf);
                    mma16816(ctx[i][2 * njp + 1], pa[i], vf + 2);
                }
            }
        }
    }

    // ---- reduce ctx across the two key-half warps, write fp16 ----
    __syncthreads();
    float* cb = (float*)(smraw + 2 * TILE);   // overlay on V buffers (dead now)
    if (wn == 0) {
#pragma unroll
        for (int i = 0; i < 2; i++)
#pragma unroll
            for (int j = 0; j < 8; j++) {
                int row = wm + i * 16 + (lane >> 2);
                int d = j * 8 + (lane & 3) * 2;
                cb[row * 68 + d]           = ctx[i][j][0];
                cb[row * 68 + d + 1]       = ctx[i][j][1];
                cb[(row + 8) * 68 + d]     = ctx[i][j][2];
                cb[(row + 8) * 68 + d + 1] = ctx[i][j][3];
            }
    }
    __syncthreads();
    if (wn == 64) {
#pragma unroll
        for (int i = 0; i < 2; i++)
#pragma unroll
            for (int j = 0; j < 8; j++) {
                int row = wm + i * 16 + (lane >> 2);
                int d = j * 8 + (lane & 3) * 2;
                cb[row * 68 + d]           += ctx[i][j][0];
                cb[row * 68 + d + 1]       += ctx[i][j][1];
                cb[(row + 8) * 68 + d]     += ctx[i][j][2];
                cb[(row + 8) * 68 + d + 1] += ctx[i][j][3];
            }
    }
    __syncthreads();
#pragma unroll
    for (int it = 0; it < 16; it++) {
        int idx = tid + it * 128;
        int row = idx >> 5, d2 = (idx & 31) * 2;
        uint32_t hv = packh2(cb[row * 68 + d2], cb[row * 68 + d2 + 1]);
        *(uint32_t*)&ctxh[((size_t)(b * T + q0 + row)) * DM + h * DH + d2] = hv;
    }

    // ---- zero-fill strictly-future weight columns ----
    const int c0 = nkt * 128;
    if (c0 < T) {
        const int cpr = (T - c0) >> 2;
        float4 z = make_float4(0.f, 0.f, 0.f, 0.f);
        for (int idx = tid; idx < 64 * cpr; idx += 128) {
            int row = idx / cpr, c = idx % cpr;
            *(float4*)&weights[((size_t)bh * T + q0 + row) * T + c0 + c * 4] = z;
        }
    }
}

// ---------------------------------------------------------------------------
extern "C" void kernel_launch(void* const* d_in, const int* in_sizes, int n_in,
                              void* d_out, int out_size)
{
    const float* x     = (const float*)d_in[0];
    const float* w_qkv = (const float*)d_in[1];
    const float* b_qkv = (const float*)d_in[2];
    const float* w_out = (const float*)d_in[3];
    const float* b_out = (const float*)d_in[4];

    float* out     = (float*)d_out;               // [B,T,DM] fp32
    float* weights = out + (size_t)MROWS * DM;    // [B,H,T,T] fp32

    __half *xh, *wqkvT, *woutT, *qkvh, *ctxh;
    cudaGetSymbolAddress((void**)&xh,    g_xh);
    cudaGetSymbolAddress((void**)&wqkvT, g_wqkvT);
    cudaGetSymbolAddress((void**)&woutT, g_woutT);
    cudaGetSymbolAddress((void**)&qkvh,  g_qkvh);
    cudaGetSymbolAddress((void**)&ctxh,  g_ctxh);

    const int SMEM = 4 * TILE * 2;   // 73728 bytes
    cudaFuncSetAttribute(gemm_h<true>,  cudaFuncAttributeMaxDynamicSharedMemorySize, SMEM);
    cudaFuncSetAttribute(gemm_h<false>, cudaFuncAttributeMaxDynamicSharedMemorySize, SMEM);
    cudaFuncSetAttribute(attn_fused,    cudaFuncAttributeMaxDynamicSharedMemorySize, SMEM);

    // 0) fp16 conversions
    cvt_x_kernel<<<(MROWS * DM / 8 + 255) / 256, 256>>>(x, xh, MROWS * DM / 8);
    cvt_wT_kernel<<<dim3(QKN / 32, DM / 32), dim3(32, 8)>>>(w_qkv, wqkvT, QKN);
    cvt_wT_kernel<<<dim3(DM / 32, DM / 32), dim3(32, 8)>>>(w_out, woutT, DM);

    // 1) QKV projection (fp16 out)
    dim3 g1(QKN / 128, MROWS / 128);
    gemm_h<true><<<g1, 256, SMEM>>>(xh, wqkvT, b_qkv, qkvh, MROWS, QKN, DM);

    // 2) Fused attention
    dim3 g2(T / 64, NH, BATCH);
    attn_fused<<<g2, 128, SMEM>>>(qkvh, weights, ctxh);

    // 3) Output projection (fp32 out)
    dim3 g3(DM / 128, MROWS / 128);
    gemm_h<false><<<g3, 256, SMEM>>>(ctxh, woutT, b_out, out, MROWS, DM, DM);
}